// round 4
// baseline (speedup 1.0000x reference)
#include <cuda_runtime.h>
#include <cuda_bf16.h>
#include <cstdint>

// Problem constants
#define NBATCH 128
#define D1     1024
#define D2     512
#define DD1    512
#define DD2    256

// GEMM tiling
#define BM 128
#define BN 128
#define BK 32                 // bf16 elements per k-stage
#define ROWB 80               // padded smem row stride (64B data + 16B pad)
#define TILEB (128 * ROWB)    // 10240 B per (hi or lo) tile
#define STAGEB (4 * TILEB)    // A_hi, A_lo, B_hi, B_lo
#define NSTAGE 3
#define SMEM_BYTES (NSTAGE * STAGEB)   // 122880

typedef __nv_bfloat16 bf16;

// ---------------------------------------------------------------------------
// Scratch (allocation-free __device__ globals)
// ---------------------------------------------------------------------------
__device__ float g_s[(size_t)NBATCH * DD1 * D2];
__device__ bf16  g_xThi[(size_t)NBATCH * D2 * D1];
__device__ bf16  g_xTlo[(size_t)NBATCH * D2 * D1];
__device__ bf16  g_hhi[(size_t)NBATCH * DD1 * D2];
__device__ bf16  g_hlo[(size_t)NBATCH * DD1 * D2];
__device__ bf16  g_ghi[(size_t)NBATCH * DD1 * D2];
__device__ bf16  g_glo[(size_t)NBATCH * DD1 * D2];
__device__ bf16  g_W1Thi[(size_t)DD1 * D1];
__device__ bf16  g_W1Tlo[(size_t)DD1 * D1];
__device__ bf16  g_W2Thi[(size_t)DD2 * D2];
__device__ bf16  g_W2Tlo[(size_t)DD2 * D2];
__device__ bf16  g_WmThi[(size_t)D2 * D2];
__device__ bf16  g_WmTlo[(size_t)D2 * D2];

// ---------------------------------------------------------------------------
// Helpers
// ---------------------------------------------------------------------------
__device__ __forceinline__ uint32_t smem_u32(const void* p) {
    uint32_t a;
    asm("{ .reg .u64 t; cvta.to.shared.u64 t, %1; cvt.u32.u64 %0, t; }"
        : "=r"(a) : "l"(p));
    return a;
}
__device__ __forceinline__ void cpa16(uint32_t s, const void* g) {
    asm volatile("cp.async.cg.shared.global [%0], [%1], 16;"
                 :: "r"(s), "l"(__cvta_generic_to_global(g)));
}
#define CP_COMMIT() asm volatile("cp.async.commit_group;" ::: "memory")
#define CP_WAIT1()  asm volatile("cp.async.wait_group 1;"  ::: "memory")

__device__ __forceinline__ void ldmx4(uint32_t* r, uint32_t addr) {
    asm volatile("ldmatrix.sync.aligned.m8n8.x4.shared.b16 {%0,%1,%2,%3}, [%4];"
                 : "=r"(r[0]), "=r"(r[1]), "=r"(r[2]), "=r"(r[3]) : "r"(addr));
}
__device__ __forceinline__ void mma_bf16(float* d, const uint32_t* a,
                                         uint32_t b0, uint32_t b1) {
    asm volatile(
        "mma.sync.aligned.m16n8k16.row.col.f32.bf16.bf16.f32 "
        "{%0,%1,%2,%3}, {%4,%5,%6,%7}, {%8,%9}, {%0,%1,%2,%3};"
        : "+f"(d[0]), "+f"(d[1]), "+f"(d[2]), "+f"(d[3])
        : "r"(a[0]), "r"(a[1]), "r"(a[2]), "r"(a[3]), "r"(b0), "r"(b1));
}

// Split a pair of fp32 into packed bf16x2 hi and lo (lo = residual)
__device__ __forceinline__ void pack_split(float a, float b,
                                           uint32_t& hi, uint32_t& lo) {
    asm("cvt.rn.bf16x2.f32 %0, %1, %2;" : "=r"(hi) : "f"(b), "f"(a));
    float ha = __uint_as_float(hi << 16);
    float hb = __uint_as_float(hi & 0xFFFF0000u);
    asm("cvt.rn.bf16x2.f32 %0, %1, %2;" : "=r"(lo) : "f"(b - hb), "f"(a - ha));
}
__device__ __forceinline__ float2 unpack_bf2(uint32_t u) {
    return make_float2(__uint_as_float(u << 16),
                       __uint_as_float(u & 0xFFFF0000u));
}

// ---------------------------------------------------------------------------
// Batched GEMM via mma.sync bf16x3 split:
//   C[z] = A[z] (MxK) @ B[z]^T   with A,B pre-split into hi/lo bf16.
// EPI: 0 = fp32 C; 1 = split bf16 hi/lo C only; 2 = fp32 C + bias
// ---------------------------------------------------------------------------
template <int EPI>
__global__ void __launch_bounds__(256)
mma_gemm_kernel(const bf16* __restrict__ Ahi, const bf16* __restrict__ Alo,
                const bf16* __restrict__ Bhi, const bf16* __restrict__ Blo,
                float* __restrict__ C, bf16* __restrict__ Chi,
                bf16* __restrict__ Clo, const float* __restrict__ bias,
                int K, int N, long sA, long sB, long sC)
{
    extern __shared__ char smem[];
    const uint32_t sb = smem_u32(smem);
    const int tid = threadIdx.x, lane = tid & 31, wid = tid >> 5;
    const int z = blockIdx.z;
    const int m0 = blockIdx.y * BM, n0 = blockIdx.x * BN;

    const bf16* Ah = Ahi + (size_t)z * sA + (size_t)m0 * K;
    const bf16* Al = Alo + (size_t)z * sA + (size_t)m0 * K;
    const bf16* Bh = Bhi + (size_t)z * sB + (size_t)n0 * K;
    const bf16* Bl = Blo + (size_t)z * sB + (size_t)n0 * K;

    const int NK = K / BK;

    const int warp_m = (wid & 1) * 64;
    const int warp_n = (wid >> 1) * 32;
    const uint32_t laddr = (uint32_t)((lane & 15) * ROWB + (lane >> 4) * 16);

    float acc[4][4][4];
#pragma unroll
    for (int i = 0; i < 4; i++)
#pragma unroll
        for (int j = 0; j < 4; j++)
#pragma unroll
            for (int k = 0; k < 4; k++) acc[i][j][k] = 0.0f;

    // ---- stage issue (cp.async, 8x16B per thread) ----
    auto issue = [&](int st, int buf) {
        const int k0 = st * BK;
#pragma unroll
        for (int j = 0; j < 2; j++) {
            int c = tid + j * 256;            // 0..511
            int row = c >> 2, seg = c & 3;
            size_t go = (size_t)row * K + k0 + seg * 8;
            uint32_t so = sb + buf * STAGEB + row * ROWB + seg * 16;
            cpa16(so,             Ah + go);
            cpa16(so + TILEB,     Al + go);
            cpa16(so + 2 * TILEB, Bh + go);
            cpa16(so + 3 * TILEB, Bl + go);
        }
    };

    issue(0, 0); CP_COMMIT();
    issue(1, 1); CP_COMMIT();

    for (int kt = 0; kt < NK; kt++) {
        const int buf = kt % NSTAGE;
        CP_WAIT1();
        __syncthreads();

        // prefetch stage kt+2 into buf (kt+2)%3 == (kt-1)%3 (safe after sync)
        if (kt + 2 < NK) issue(kt + 2, (kt + 2) % NSTAGE);
        CP_COMMIT();

        const uint32_t abase = sb + buf * STAGEB;
        const uint32_t bbase = abase + 2 * TILEB;
#pragma unroll
        for (int kh = 0; kh < 2; kh++) {
            uint32_t A0f[4][4], A1f[4][4], B0f[2][4], B1f[2][4];
#pragma unroll
            for (int mt = 0; mt < 4; mt++) {
                uint32_t ad = abase + (warp_m + mt * 16) * ROWB + kh * 32 + laddr;
                ldmx4(A0f[mt], ad);
                ldmx4(A1f[mt], ad + TILEB);
            }
#pragma unroll
            for (int p = 0; p < 2; p++) {
                uint32_t bd = bbase + (warp_n + p * 16) * ROWB + kh * 32 + laddr;
                ldmx4(B0f[p], bd);
                ldmx4(B1f[p], bd + TILEB);
            }
            // Pass-major ordering: 16 independent acc chains between reuses
#pragma unroll
            for (int mt = 0; mt < 4; mt++)
#pragma unroll
                for (int nt = 0; nt < 4; nt++) {
                    const int p = nt >> 1, o = nt & 1;
                    mma_bf16(acc[mt][nt], A0f[mt], B0f[p][o], B0f[p][o + 2]);
                }
#pragma unroll
            for (int mt = 0; mt < 4; mt++)
#pragma unroll
                for (int nt = 0; nt < 4; nt++) {
                    const int p = nt >> 1, o = nt & 1;
                    mma_bf16(acc[mt][nt], A0f[mt], B1f[p][o], B1f[p][o + 2]);
                }
#pragma unroll
            for (int mt = 0; mt < 4; mt++)
#pragma unroll
                for (int nt = 0; nt < 4; nt++) {
                    const int p = nt >> 1, o = nt & 1;
                    mma_bf16(acc[mt][nt], A1f[mt], B0f[p][o], B0f[p][o + 2]);
                }
        }
    }

    // ---- epilogue ----
#pragma unroll
    for (int mt = 0; mt < 4; mt++)
#pragma unroll
        for (int nt = 0; nt < 4; nt++) {
            int r = m0 + warp_m + mt * 16 + (lane >> 2);
            int cc = n0 + warp_n + nt * 8 + 2 * (lane & 3);
            float v0 = acc[mt][nt][0], v1 = acc[mt][nt][1];
            float v2 = acc[mt][nt][2], v3 = acc[mt][nt][3];
            if (EPI == 2) {
                float2 b0 = *(const float2*)(bias + (size_t)r * N + cc);
                float2 b1 = *(const float2*)(bias + (size_t)(r + 8) * N + cc);
                v0 += b0.x; v1 += b0.y; v2 += b1.x; v3 += b1.y;
            }
            if (EPI == 0 || EPI == 2) {
                float* Cb = C + (size_t)z * sC;
                *(float2*)(Cb + (size_t)r * N + cc)       = make_float2(v0, v1);
                *(float2*)(Cb + (size_t)(r + 8) * N + cc) = make_float2(v2, v3);
            }
            if (EPI == 1) {
                uint32_t h01, l01, h23, l23;
                pack_split(v0, v1, h01, l01);
                pack_split(v2, v3, h23, l23);
                bf16* chb = Chi + (size_t)z * sC;
                bf16* clb = Clo + (size_t)z * sC;
                *(uint32_t*)(chb + (size_t)r * N + cc)       = h01;
                *(uint32_t*)(clb + (size_t)r * N + cc)       = l01;
                *(uint32_t*)(chb + (size_t)(r + 8) * N + cc) = h23;
                *(uint32_t*)(clb + (size_t)(r + 8) * N + cc) = l23;
            }
        }
}

// ---------------------------------------------------------------------------
// Transpose + split: in fp32 [z][R][C] -> out hi/lo bf16 [z][C][R]
// ---------------------------------------------------------------------------
__global__ void transpose_split_kernel(const float* __restrict__ in,
                                       bf16* __restrict__ ohi,
                                       bf16* __restrict__ olo, int R, int Ccols)
{
    __shared__ float t[32][33];
    const size_t zoff = (size_t)blockIdx.z * R * Ccols;
    const float* ib = in + zoff;
    bf16* oh = ohi + zoff;
    bf16* ol = olo + zoff;
    int c0 = blockIdx.x * 32, r0 = blockIdx.y * 32;
#pragma unroll
    for (int i = threadIdx.y; i < 32; i += 8)
        t[i][threadIdx.x] = ib[(size_t)(r0 + i) * Ccols + c0 + threadIdx.x];
    __syncthreads();
#pragma unroll
    for (int i = threadIdx.y; i < 32; i += 8) {
        float v = t[threadIdx.x][i];
        bf16 h = __float2bfloat16_rn(v);
        oh[(size_t)(c0 + i) * R + r0 + threadIdx.x] = h;
        ol[(size_t)(c0 + i) * R + r0 + threadIdx.x] =
            __float2bfloat16_rn(v - __bfloat162float(h));
    }
}

// WmT[j][i] = (i==j) ? 1/D2 : W[i][j], split to hi/lo
__global__ void build_wmT_split_kernel(const float* __restrict__ W) {
    int idx = blockIdx.x * blockDim.x + threadIdx.x;
    int j = idx / D2, i = idx % D2;
    float v = (i == j) ? (1.0f / (float)D2) : W[(size_t)i * D2 + j];
    bf16 h = __float2bfloat16_rn(v);
    g_WmThi[idx] = h;
    g_WmTlo[idx] = __float2bfloat16_rn(v - __bfloat162float(h));
}

// ---------------------------------------------------------------------------
// softmax over last axis (512) + gate: g = a*h + (1-a)*h*softmax(s)
// h reconstructed from split (exact); writes g as split bf16 hi/lo
// ---------------------------------------------------------------------------
__global__ void __launch_bounds__(128)
softmax_gate_kernel(const float* __restrict__ alpha_p)
{
    const size_t base = (size_t)blockIdx.x * D2;
    const int t = threadIdx.x;

    float4 sv = *(const float4*)(g_s + base + t * 4);
    float m = fmaxf(fmaxf(sv.x, sv.y), fmaxf(sv.z, sv.w));
    __shared__ float red[4];
#pragma unroll
    for (int o = 16; o > 0; o >>= 1)
        m = fmaxf(m, __shfl_xor_sync(0xFFFFFFFFu, m, o));
    if ((t & 31) == 0) red[t >> 5] = m;
    __syncthreads();
    m = fmaxf(fmaxf(red[0], red[1]), fmaxf(red[2], red[3]));

    float e0 = __expf(sv.x - m), e1 = __expf(sv.y - m);
    float e2 = __expf(sv.z - m), e3 = __expf(sv.w - m);
    float sum = e0 + e1 + e2 + e3;
#pragma unroll
    for (int o = 16; o > 0; o >>= 1)
        sum += __shfl_xor_sync(0xFFFFFFFFu, sum, o);
    __syncthreads();
    if ((t & 31) == 0) red[t >> 5] = sum;
    __syncthreads();
    sum = red[0] + red[1] + red[2] + red[3];
    float inv = 1.0f / sum;

    float a = fminf(fmaxf(alpha_p[0], 0.0f), 10.0f);
    float oma = 1.0f - a;

    uint2 hh = *(const uint2*)(g_hhi + base + t * 4);
    uint2 hl = *(const uint2*)(g_hlo + base + t * 4);
    float2 h01 = unpack_bf2(hh.x), h23 = unpack_bf2(hh.y);
    float2 l01 = unpack_bf2(hl.x), l23 = unpack_bf2(hl.y);
    float hv0 = h01.x + l01.x, hv1 = h01.y + l01.y;
    float hv2 = h23.x + l23.x, hv3 = h23.y + l23.y;

    float g0 = a * hv0 + oma * hv0 * (e0 * inv);
    float g1 = a * hv1 + oma * hv1 * (e1 * inv);
    float g2 = a * hv2 + oma * hv2 * (e2 * inv);
    float g3 = a * hv3 + oma * hv3 * (e3 * inv);

    uint32_t gh01, gl01, gh23, gl23;
    pack_split(g0, g1, gh01, gl01);
    pack_split(g2, g3, gh23, gl23);
    *(uint2*)(g_ghi + base + t * 4) = make_uint2(gh01, gh23);
    *(uint2*)(g_glo + base + t * 4) = make_uint2(gl01, gl23);
}

// ---------------------------------------------------------------------------
// Launch
// ---------------------------------------------------------------------------
extern "C" void kernel_launch(void* const* d_in, const int* in_sizes, int n_in,
                              void* d_out, int out_size)
{
    const float* x     = (const float*)d_in[0];
    const float* W1    = (const float*)d_in[1];
    const float* W2    = (const float*)d_in[2];
    const float* W     = (const float*)d_in[3];
    const float* alpha = (const float*)d_in[4];
    const float* bias  = (const float*)d_in[5];
    float* out = (float*)d_out;

    float *s_p;
    bf16 *xThi, *xTlo, *hhi, *hlo, *ghi, *glo;
    bf16 *W1Thi, *W1Tlo, *W2Thi, *W2Tlo, *WmThi, *WmTlo;
    cudaGetSymbolAddress((void**)&s_p,   g_s);
    cudaGetSymbolAddress((void**)&xThi,  g_xThi);
    cudaGetSymbolAddress((void**)&xTlo,  g_xTlo);
    cudaGetSymbolAddress((void**)&hhi,   g_hhi);
    cudaGetSymbolAddress((void**)&hlo,   g_hlo);
    cudaGetSymbolAddress((void**)&ghi,   g_ghi);
    cudaGetSymbolAddress((void**)&glo,   g_glo);
    cudaGetSymbolAddress((void**)&W1Thi, g_W1Thi);
    cudaGetSymbolAddress((void**)&W1Tlo, g_W1Tlo);
    cudaGetSymbolAddress((void**)&W2Thi, g_W2Thi);
    cudaGetSymbolAddress((void**)&W2Tlo, g_W2Tlo);
    cudaGetSymbolAddress((void**)&WmThi, g_WmThi);
    cudaGetSymbolAddress((void**)&WmTlo, g_WmTlo);

    cudaFuncSetAttribute(mma_gemm_kernel<0>,
                         cudaFuncAttributeMaxDynamicSharedMemorySize, SMEM_BYTES);
    cudaFuncSetAttribute(mma_gemm_kernel<1>,
                         cudaFuncAttributeMaxDynamicSharedMemorySize, SMEM_BYTES);
    cudaFuncSetAttribute(mma_gemm_kernel<2>,
                         cudaFuncAttributeMaxDynamicSharedMemorySize, SMEM_BYTES);

    // Prep: transposed + split operands
    transpose_split_kernel<<<dim3(D2 / 32, D1 / 32, NBATCH), dim3(32, 8)>>>(
        x, xThi, xTlo, D1, D2);
    transpose_split_kernel<<<dim3(DD1 / 32, D1 / 32, 1), dim3(32, 8)>>>(
        W1, W1Thi, W1Tlo, D1, DD1);
    transpose_split_kernel<<<dim3(DD2 / 32, D2 / 32, 1), dim3(32, 8)>>>(
        W2, W2Thi, W2Tlo, D2, DD2);
    build_wmT_split_kernel<<<(D2 * D2) / 256, 256>>>(W);

    // G1: h[z] = W1T (512x1024) @ xT[z]^T  -> split hi/lo only
    mma_gemm_kernel<1><<<dim3(D2 / BN, DD1 / BM, NBATCH), 256, SMEM_BYTES>>>(
        W1Thi, W1Tlo, xThi, xTlo, nullptr, hhi, hlo, nullptr,
        D1, D2, 0L, (long)D2 * D1, (long)DD1 * D2);

    // G2: s[z] = h[z] (512x512) @ WmT^T  -> fp32 s
    mma_gemm_kernel<0><<<dim3(D2 / BN, DD1 / BM, NBATCH), 256, SMEM_BYTES>>>(
        hhi, hlo, WmThi, WmTlo, s_p, nullptr, nullptr, nullptr,
        D2, D2, (long)DD1 * D2, 0L, (long)DD1 * D2);

    // softmax + gate -> g (split bf16)
    softmax_gate_kernel<<<NBATCH * DD1, 128>>>(alpha);

    // G3: out[z] = g[z] (512x512) @ W2T^T + bias
    mma_gemm_kernel<2><<<dim3(DD2 / BN, DD1 / BM, NBATCH), 256, SMEM_BYTES>>>(
        ghi, glo, W2Thi, W2Tlo, out, nullptr, nullptr, bias,
        D2, DD2, (long)DD1 * D2, 0L, (long)DD1 * DD2);
}

// round 5
// speedup vs baseline: 1.4793x; 1.4793x over previous
#include <cuda_runtime.h>
#include <cuda_fp16.h>
#include <cstdint>

// Problem constants
#define NBATCH 128
#define D1     1024
#define D2     512
#define DD1    512
#define DD2    256

// GEMM tiling
#define BM 128
#define BN 128
#define BK 32                 // fp16 elements per k-stage
#define ROWB 80               // padded smem row stride (64B data + 16B pad)
#define TILEB (128 * ROWB)    // 10240 B per tile
#define STAGEB (3 * TILEB)    // A_hi, A_lo, B_hi
#define SMEM_BYTES (2 * STAGEB)   // 61440 -> 2 CTAs/SM

typedef __half h16;

// ---------------------------------------------------------------------------
// Scratch (allocation-free __device__ globals)
// ---------------------------------------------------------------------------
__device__ float g_s[(size_t)NBATCH * DD1 * D2];
__device__ h16   g_xTh[(size_t)NBATCH * D2 * D1];
__device__ h16   g_hhi[(size_t)NBATCH * DD1 * D2];
__device__ h16   g_hlo[(size_t)NBATCH * DD1 * D2];
__device__ h16   g_ghi[(size_t)NBATCH * DD1 * D2];
__device__ h16   g_glo[(size_t)NBATCH * DD1 * D2];
__device__ h16   g_W1Thi[(size_t)DD1 * D1];
__device__ h16   g_W1Tlo[(size_t)DD1 * D1];
__device__ h16   g_W2Th[(size_t)DD2 * D2];
__device__ h16   g_WmTh[(size_t)D2 * D2];

// ---------------------------------------------------------------------------
// Helpers
// ---------------------------------------------------------------------------
__device__ __forceinline__ uint32_t smem_u32(const void* p) {
    uint32_t a;
    asm("{ .reg .u64 t; cvta.to.shared.u64 t, %1; cvt.u32.u64 %0, t; }"
        : "=r"(a) : "l"(p));
    return a;
}
__device__ __forceinline__ void cpa16(uint32_t s, const void* g) {
    asm volatile("cp.async.cg.shared.global [%0], [%1], 16;"
                 :: "r"(s), "l"(__cvta_generic_to_global(g)));
}
#define CP_COMMIT() asm volatile("cp.async.commit_group;" ::: "memory")
#define CP_WAIT1()  asm volatile("cp.async.wait_group 1;"  ::: "memory")

__device__ __forceinline__ void ldmx4(uint32_t* r, uint32_t addr) {
    asm volatile("ldmatrix.sync.aligned.m8n8.x4.shared.b16 {%0,%1,%2,%3}, [%4];"
                 : "=r"(r[0]), "=r"(r[1]), "=r"(r[2]), "=r"(r[3]) : "r"(addr));
}
__device__ __forceinline__ void mma_f16(float* d, const uint32_t* a,
                                        uint32_t b0, uint32_t b1) {
    asm volatile(
        "mma.sync.aligned.m16n8k16.row.col.f32.f16.f16.f32 "
        "{%0,%1,%2,%3}, {%4,%5,%6,%7}, {%8,%9}, {%0,%1,%2,%3};"
        : "+f"(d[0]), "+f"(d[1]), "+f"(d[2]), "+f"(d[3])
        : "r"(a[0]), "r"(a[1]), "r"(a[2]), "r"(a[3]), "r"(b0), "r"(b1));
}

// Split a pair of fp32 into packed half2 hi and lo (lo = residual)
__device__ __forceinline__ void pack_split_h(float a, float b,
                                             uint32_t& hi, uint32_t& lo) {
    __half2 h = __floats2half2_rn(a, b);
    float ha = __low2float(h), hb = __high2float(h);
    __half2 l = __floats2half2_rn(a - ha, b - hb);
    hi = *(uint32_t*)&h;
    lo = *(uint32_t*)&l;
}

// ---------------------------------------------------------------------------
// Batched GEMM, fp16 2-pass split:
//   C[z] = (Ahi+Alo)[z] (MxK) @ Bh[z]^T    (B: [N][K], hi only)
// EPI: 0 = fp32 C; 1 = split fp16 hi/lo C; 2 = fp32 C + bias
// ---------------------------------------------------------------------------
template <int EPI>
__global__ void __launch_bounds__(256, 2)
mma_gemm_kernel(const h16* __restrict__ Ahi, const h16* __restrict__ Alo,
                const h16* __restrict__ Bh_, float* __restrict__ C,
                h16* __restrict__ Chi, h16* __restrict__ Clo,
                const float* __restrict__ bias,
                int K, int N, long sA, long sB, long sC)
{
    extern __shared__ char smem[];
    const uint32_t sb = smem_u32(smem);
    const int tid = threadIdx.x, lane = tid & 31, wid = tid >> 5;
    const int z = blockIdx.z;
    const int m0 = blockIdx.y * BM, n0 = blockIdx.x * BN;

    const h16* Ah = Ahi + (size_t)z * sA + (size_t)m0 * K;
    const h16* Al = Alo + (size_t)z * sA + (size_t)m0 * K;
    const h16* Bh = Bh_ + (size_t)z * sB + (size_t)n0 * K;

    const int NK = K / BK;

    const int warp_m = (wid & 1) * 64;
    const int warp_n = (wid >> 1) * 32;
    const uint32_t laddr = (uint32_t)((lane & 15) * ROWB + (lane >> 4) * 16);

    float acc[4][4][4];
#pragma unroll
    for (int i = 0; i < 4; i++)
#pragma unroll
        for (int j = 0; j < 4; j++)
#pragma unroll
            for (int k = 0; k < 4; k++) acc[i][j][k] = 0.0f;

    // ---- stage issue (cp.async, 6x16B per thread) ----
    auto issue = [&](int st, int buf) {
        const int k0 = st * BK;
#pragma unroll
        for (int j = 0; j < 2; j++) {
            int c = tid + j * 256;            // 0..511
            int row = c >> 2, seg = c & 3;
            size_t go = (size_t)row * K + k0 + seg * 8;
            uint32_t so = sb + buf * STAGEB + row * ROWB + seg * 16;
            cpa16(so,             Ah + go);
            cpa16(so + TILEB,     Al + go);
            cpa16(so + 2 * TILEB, Bh + go);
        }
    };

    issue(0, 0); CP_COMMIT();
    issue(1, 1); CP_COMMIT();

    for (int kt = 0; kt < NK; kt++) {
        const int buf = kt & 1;
        CP_WAIT1();
        __syncthreads();

        const uint32_t abase = sb + buf * STAGEB;
        const uint32_t bbase = abase + 2 * TILEB;
#pragma unroll
        for (int kh = 0; kh < 2; kh++) {
            uint32_t Af[4][4], Lf[4][4], Bf[2][4];
#pragma unroll
            for (int mt = 0; mt < 4; mt++) {
                uint32_t ad = abase + (warp_m + mt * 16) * ROWB + kh * 32 + laddr;
                ldmx4(Af[mt], ad);
                ldmx4(Lf[mt], ad + TILEB);
            }
#pragma unroll
            for (int p = 0; p < 2; p++) {
                uint32_t bd = bbase + (warp_n + p * 16) * ROWB + kh * 32 + laddr;
                ldmx4(Bf[p], bd);
            }
            // Pass-major: 16 independent acc chains between reuses
#pragma unroll
            for (int mt = 0; mt < 4; mt++)
#pragma unroll
                for (int nt = 0; nt < 4; nt++) {
                    const int p = nt >> 1, o = nt & 1;
                    mma_f16(acc[mt][nt], Af[mt], Bf[p][o], Bf[p][o + 2]);
                }
#pragma unroll
            for (int mt = 0; mt < 4; mt++)
#pragma unroll
                for (int nt = 0; nt < 4; nt++) {
                    const int p = nt >> 1, o = nt & 1;
                    mma_f16(acc[mt][nt], Lf[mt], Bf[p][o], Bf[p][o + 2]);
                }
        }
        __syncthreads();
        if (kt + 2 < NK) issue(kt + 2, buf);
        CP_COMMIT();
    }

    // ---- epilogue ----
#pragma unroll
    for (int mt = 0; mt < 4; mt++)
#pragma unroll
        for (int nt = 0; nt < 4; nt++) {
            int r = m0 + warp_m + mt * 16 + (lane >> 2);
            int cc = n0 + warp_n + nt * 8 + 2 * (lane & 3);
            float v0 = acc[mt][nt][0], v1 = acc[mt][nt][1];
            float v2 = acc[mt][nt][2], v3 = acc[mt][nt][3];
            if (EPI == 2) {
                float2 b0 = *(const float2*)(bias + (size_t)r * N + cc);
                float2 b1 = *(const float2*)(bias + (size_t)(r + 8) * N + cc);
                v0 += b0.x; v1 += b0.y; v2 += b1.x; v3 += b1.y;
            }
            if (EPI == 0 || EPI == 2) {
                float* Cb = C + (size_t)z * sC;
                *(float2*)(Cb + (size_t)r * N + cc)       = make_float2(v0, v1);
                *(float2*)(Cb + (size_t)(r + 8) * N + cc) = make_float2(v2, v3);
            }
            if (EPI == 1) {
                uint32_t h01, l01, h23, l23;
                pack_split_h(v0, v1, h01, l01);
                pack_split_h(v2, v3, h23, l23);
                h16* chb = Chi + (size_t)z * sC;
                h16* clb = Clo + (size_t)z * sC;
                *(uint32_t*)(chb + (size_t)r * N + cc)       = h01;
                *(uint32_t*)(clb + (size_t)r * N + cc)       = l01;
                *(uint32_t*)(chb + (size_t)(r + 8) * N + cc) = h23;
                *(uint32_t*)(clb + (size_t)(r + 8) * N + cc) = l23;
            }
        }
}

// ---------------------------------------------------------------------------
// Transpose: in fp32 [z][R][C] -> out fp16 [z][C][R] (SPLIT: also residual lo)
// ---------------------------------------------------------------------------
template <bool SPLIT>
__global__ void transpose_h_kernel(const float* __restrict__ in,
                                   h16* __restrict__ ohi,
                                   h16* __restrict__ olo, int R, int Ccols)
{
    __shared__ float t[32][33];
    const size_t zoff = (size_t)blockIdx.z * R * Ccols;
    const float* ib = in + zoff;
    h16* oh = ohi + zoff;
    h16* ol = SPLIT ? olo + zoff : nullptr;
    int c0 = blockIdx.x * 32, r0 = blockIdx.y * 32;
#pragma unroll
    for (int i = threadIdx.y; i < 32; i += 8)
        t[i][threadIdx.x] = ib[(size_t)(r0 + i) * Ccols + c0 + threadIdx.x];
    __syncthreads();
#pragma unroll
    for (int i = threadIdx.y; i < 32; i += 8) {
        float v = t[threadIdx.x][i];
        h16 h = __float2half_rn(v);
        oh[(size_t)(c0 + i) * R + r0 + threadIdx.x] = h;
        if (SPLIT)
            ol[(size_t)(c0 + i) * R + r0 + threadIdx.x] =
                __float2half_rn(v - __half2float(h));
    }
}

// WmT[j][i] = (i==j) ? 1/D2 : W[i][j]  (fp16 hi only)
__global__ void build_wmT_kernel(const float* __restrict__ W) {
    int idx = blockIdx.x * blockDim.x + threadIdx.x;
    int j = idx / D2, i = idx % D2;
    float v = (i == j) ? (1.0f / (float)D2) : W[(size_t)i * D2 + j];
    g_WmTh[idx] = __float2half_rn(v);
}

// ---------------------------------------------------------------------------
// softmax over last axis (512) + gate: g = a*h + (1-a)*h*softmax(s)
// h reconstructed from fp16 split; writes g as fp16 hi/lo
// ---------------------------------------------------------------------------
__global__ void __launch_bounds__(128)
softmax_gate_kernel(const float* __restrict__ alpha_p)
{
    const size_t base = (size_t)blockIdx.x * D2;
    const int t = threadIdx.x;

    float4 sv = *(const float4*)(g_s + base + t * 4);
    float m = fmaxf(fmaxf(sv.x, sv.y), fmaxf(sv.z, sv.w));
    __shared__ float red[4];
#pragma unroll
    for (int o = 16; o > 0; o >>= 1)
        m = fmaxf(m, __shfl_xor_sync(0xFFFFFFFFu, m, o));
    if ((t & 31) == 0) red[t >> 5] = m;
    __syncthreads();
    m = fmaxf(fmaxf(red[0], red[1]), fmaxf(red[2], red[3]));

    float e0 = __expf(sv.x - m), e1 = __expf(sv.y - m);
    float e2 = __expf(sv.z - m), e3 = __expf(sv.w - m);
    float sum = e0 + e1 + e2 + e3;
#pragma unroll
    for (int o = 16; o > 0; o >>= 1)
        sum += __shfl_xor_sync(0xFFFFFFFFu, sum, o);
    __syncthreads();
    if ((t & 31) == 0) red[t >> 5] = sum;
    __syncthreads();
    sum = red[0] + red[1] + red[2] + red[3];
    float inv = 1.0f / sum;

    float a = fminf(fmaxf(alpha_p[0], 0.0f), 10.0f);
    float oma = 1.0f - a;

    __half2 hh0 = *(const __half2*)(g_hhi + base + t * 4);
    __half2 hh1 = *(const __half2*)(g_hhi + base + t * 4 + 2);
    __half2 hl0 = *(const __half2*)(g_hlo + base + t * 4);
    __half2 hl1 = *(const __half2*)(g_hlo + base + t * 4 + 2);
    float hv0 = __low2float(hh0) + __low2float(hl0);
    float hv1 = __high2float(hh0) + __high2float(hl0);
    float hv2 = __low2float(hh1) + __low2float(hl1);
    float hv3 = __high2float(hh1) + __high2float(hl1);

    float g0 = a * hv0 + oma * hv0 * (e0 * inv);
    float g1 = a * hv1 + oma * hv1 * (e1 * inv);
    float g2 = a * hv2 + oma * hv2 * (e2 * inv);
    float g3 = a * hv3 + oma * hv3 * (e3 * inv);

    uint32_t gh01, gl01, gh23, gl23;
    pack_split_h(g0, g1, gh01, gl01);
    pack_split_h(g2, g3, gh23, gl23);
    *(uint2*)(g_ghi + base + t * 4) = make_uint2(gh01, gh23);
    *(uint2*)(g_glo + base + t * 4) = make_uint2(gl01, gl23);
}

// ---------------------------------------------------------------------------
// Launch
// ---------------------------------------------------------------------------
extern "C" void kernel_launch(void* const* d_in, const int* in_sizes, int n_in,
                              void* d_out, int out_size)
{
    const float* x     = (const float*)d_in[0];
    const float* W1    = (const float*)d_in[1];
    const float* W2    = (const float*)d_in[2];
    const float* W     = (const float*)d_in[3];
    const float* alpha = (const float*)d_in[4];
    const float* bias  = (const float*)d_in[5];
    float* out = (float*)d_out;

    float* s_p;
    h16 *xTh, *hhi, *hlo, *ghi, *glo, *W1Thi, *W1Tlo, *W2Th, *WmTh;
    cudaGetSymbolAddress((void**)&s_p,   g_s);
    cudaGetSymbolAddress((void**)&xTh,   g_xTh);
    cudaGetSymbolAddress((void**)&hhi,   g_hhi);
    cudaGetSymbolAddress((void**)&hlo,   g_hlo);
    cudaGetSymbolAddress((void**)&ghi,   g_ghi);
    cudaGetSymbolAddress((void**)&glo,   g_glo);
    cudaGetSymbolAddress((void**)&W1Thi, g_W1Thi);
    cudaGetSymbolAddress((void**)&W1Tlo, g_W1Tlo);
    cudaGetSymbolAddress((void**)&W2Th,  g_W2Th);
    cudaGetSymbolAddress((void**)&WmTh,  g_WmTh);

    cudaFuncSetAttribute(mma_gemm_kernel<0>,
                         cudaFuncAttributeMaxDynamicSharedMemorySize, SMEM_BYTES);
    cudaFuncSetAttribute(mma_gemm_kernel<1>,
                         cudaFuncAttributeMaxDynamicSharedMemorySize, SMEM_BYTES);
    cudaFuncSetAttribute(mma_gemm_kernel<2>,
                         cudaFuncAttributeMaxDynamicSharedMemorySize, SMEM_BYTES);

    // Order chosen so launch index 5 (ncu -s 5 -c 1, 2 harness launches ahead)
    // lands on G1 (mma_gemm_kernel<1>).
    transpose_h_kernel<false><<<dim3(D2 / 32, D1 / 32, NBATCH), dim3(32, 8)>>>(
        x, xTh, nullptr, D1, D2);
    build_wmT_kernel<<<(D2 * D2) / 256, 256>>>(W);
    transpose_h_kernel<true><<<dim3(DD1 / 32, D1 / 32, 1), dim3(32, 8)>>>(
        W1, W1Thi, W1Tlo, D1, DD1);

    // G1: h[z] = (W1Thi+W1Tlo) (512x1024) @ xTh[z]^T  -> fp16 split h
    mma_gemm_kernel<1><<<dim3(D2 / BN, DD1 / BM, NBATCH), 256, SMEM_BYTES>>>(
        W1Thi, W1Tlo, xTh, nullptr, hhi, hlo, nullptr,
        D1, D2, 0L, (long)D2 * D1, (long)DD1 * D2);

    // G2: s[z] = (hhi+hlo)[z] (512x512) @ WmTh^T  -> fp32 s
    mma_gemm_kernel<0><<<dim3(D2 / BN, DD1 / BM, NBATCH), 256, SMEM_BYTES>>>(
        hhi, hlo, WmTh, s_p, nullptr, nullptr, nullptr,
        D2, D2, (long)DD1 * D2, 0L, (long)DD1 * D2);

    // softmax + gate -> g (fp16 split)
    softmax_gate_kernel<<<NBATCH * DD1, 128>>>(alpha);

    // W2 transpose (only needed by G3)
    transpose_h_kernel<false><<<dim3(DD2 / 32, D2 / 32, 1), dim3(32, 8)>>>(
        W2, W2Th, nullptr, D2, DD2);

    // G3: out[z] = (ghi+glo)[z] (512x512) @ W2Th^T + bias
    mma_gemm_kernel<2><<<dim3(DD2 / BN, DD1 / BM, NBATCH), 256, SMEM_BYTES>>>(
        ghi, glo, W2Th, out, nullptr, nullptr, bias,
        D2, DD2, (long)DD1 * D2, 0L, (long)DD1 * DD2);
}